// round 1
// baseline (speedup 1.0000x reference)
#include <cuda_runtime.h>

// Problem constants (SpectralNetLoss): W [8192,8192] f32, Y [8192,32] f32 -> scalar f32.
#define MDIM 8192
#define KDIM 32          // columns of Y
#define BR   256         // rows per block == threads per block
#define JC   256         // j-columns per block (j-chunk)
#define JT   32          // j-columns per smem tile

// Scratch (no device allocs allowed): per-row WY partials and row sums.
__device__ float g_wy[MDIM * KDIM];   // 1 MB
__device__ float g_d[MDIM];           // 32 KB

// ---------------------------------------------------------------------------
// Kernel 0: zero scratch + output scalar (d_out is poisoned each replay).
// ---------------------------------------------------------------------------
__global__ void zero_kernel(float* __restrict__ out) {
    int idx = blockIdx.x * blockDim.x + threadIdx.x;
    if (idx < MDIM * KDIM) g_wy[idx] = 0.0f;
    if (idx < MDIM)        g_d[idx]  = 0.0f;
    if (idx == 0)          out[0]    = 0.0f;
}

// ---------------------------------------------------------------------------
// Kernel 1: fused rowsum + W@Y over a (256-row x 256-col) block of W.
// Thread t owns global row (blockIdx.x*256 + t); accumulates all 32 k in
// packed f32x2 registers; one pass over W (the only big operand).
// ---------------------------------------------------------------------------
__global__ void __launch_bounds__(BR)
spectral_main_kernel(const float* __restrict__ W, const float* __restrict__ Y) {
    __shared__ float Ys[JT][KDIM];       // 4 KB   Y tile, broadcast reads
    __shared__ float Ws[JT][BR + 1];     // ~32.9 KB  W tile transposed [j][row]

    const int tid  = threadIdx.x;
    const int row0 = blockIdx.x * BR;
    const int j0   = blockIdx.y * JC;
    const int row  = row0 + tid;

    unsigned long long acc[KDIM / 2];    // 16 packed f32x2 accumulators
    #pragma unroll
    for (int i = 0; i < KDIM / 2; ++i) acc[i] = 0ull;
    float dsum = 0.0f;

    for (int jt = 0; jt < JC / JT; ++jt) {
        __syncthreads();   // previous tile fully consumed

        // Load Y tile: rows [j0 + jt*32, +32), contiguous 1024 floats.
        {
            const float4* Yg = (const float4*)(Y + (size_t)(j0 + jt * JT) * KDIM);
            ((float4*)Ys)[tid] = Yg[tid];            // 256 float4 == whole tile
        }
        // Load W tile [256 rows][32 cols] transposed into Ws[c][r].
        // idx4 -> (r = idx4>>3, c4 = idx4&7): fully coalesced 128B global lines,
        // STS banks (4*c4+s + r) % 32 are all distinct per warp -> conflict-free.
        #pragma unroll
        for (int p = 0; p < (BR * JT / 4) / BR; ++p) {   // 8
            int idx4 = tid + p * BR;
            int r  = idx4 >> 3;
            int c4 = idx4 & 7;
            float4 v = *(const float4*)(W + (size_t)(row0 + r) * MDIM
                                          + j0 + jt * JT + c4 * 4);
            Ws[c4 * 4 + 0][r] = v.x;
            Ws[c4 * 4 + 1][r] = v.y;
            Ws[c4 * 4 + 2][r] = v.z;
            Ws[c4 * 4 + 3][r] = v.w;
        }
        __syncthreads();

        // Compute: per j, 1 scalar LDS (conflict-free), 8 broadcast LDS.128,
        // 16 FFMA2 (packed f32x2), 1 FADD.
        #pragma unroll 8
        for (int jj = 0; jj < JT; ++jj) {
            float w = Ws[jj][tid];
            dsum += w;
            unsigned long long wdup;
            asm("mov.b64 %0, {%1, %1};" : "=l"(wdup) : "f"(w));
            const float4* yrow = (const float4*)&Ys[jj][0];
            #pragma unroll
            for (int q = 0; q < KDIM / 4; ++q) {         // 8
                float4 y4 = yrow[q];
                unsigned long long y01, y23;
                asm("mov.b64 %0, {%1, %2};" : "=l"(y01) : "f"(y4.x), "f"(y4.y));
                asm("mov.b64 %0, {%1, %2};" : "=l"(y23) : "f"(y4.z), "f"(y4.w));
                asm("fma.rn.f32x2 %0, %1, %2, %0;"
                    : "+l"(acc[2 * q + 0]) : "l"(wdup), "l"(y01));
                asm("fma.rn.f32x2 %0, %1, %2, %0;"
                    : "+l"(acc[2 * q + 1]) : "l"(wdup), "l"(y23));
            }
        }
    }

    // Per-(row, j-chunk) partials -> global scratch (32 chunks hit each slot).
    #pragma unroll
    for (int q = 0; q < KDIM / 2; ++q) {
        float lo, hi;
        asm("mov.b64 {%0, %1}, %2;" : "=f"(lo), "=f"(hi) : "l"(acc[q]));
        atomicAdd(&g_wy[row * KDIM + 2 * q + 0], lo);
        atomicAdd(&g_wy[row * KDIM + 2 * q + 1], hi);
    }
    atomicAdd(&g_d[row], dsum);
}

// ---------------------------------------------------------------------------
// Kernel 2: loss = sum_{i,k} Y * (Y - WY/d) / m  -> scalar.
// ---------------------------------------------------------------------------
__global__ void loss_kernel(const float* __restrict__ Y, float* __restrict__ out) {
    __shared__ float red[8];
    int row = blockIdx.x * blockDim.x + threadIdx.x;

    float dinv = 1.0f / g_d[row];
    float s = 0.0f;
    #pragma unroll
    for (int k = 0; k < KDIM; ++k) {
        float y = Y[(size_t)row * KDIM + k];
        s += y * (y - g_wy[row * KDIM + k] * dinv);
    }
    // warp reduce
    #pragma unroll
    for (int off = 16; off; off >>= 1) s += __shfl_down_sync(0xffffffffu, s, off);
    if ((threadIdx.x & 31) == 0) red[threadIdx.x >> 5] = s;
    __syncthreads();
    if (threadIdx.x < 8) {
        s = red[threadIdx.x];
        #pragma unroll
        for (int off = 4; off; off >>= 1) s += __shfl_down_sync(0xffu, s, off);
        if (threadIdx.x == 0) atomicAdd(out, s * (1.0f / (float)MDIM));
    }
}

// ---------------------------------------------------------------------------
extern "C" void kernel_launch(void* const* d_in, const int* in_sizes, int n_in,
                              void* d_out, int out_size) {
    const float* W = (const float*)d_in[0];
    const float* Y = (const float*)d_in[1];
    float* out = (float*)d_out;

    zero_kernel<<<(MDIM * KDIM + 255) / 256, 256>>>(out);

    dim3 grid(MDIM / BR, MDIM / JC);   // (32, 32)
    spectral_main_kernel<<<grid, BR>>>(W, Y);

    loss_kernel<<<MDIM / 256, 256>>>(Y, out);
}

// round 2
// speedup vs baseline: 1.9844x; 1.9844x over previous
#include <cuda_runtime.h>

typedef unsigned long long ull;

// SpectralNetLoss: W [8192,8192] f32, Y [8192,32] f32 -> scalar f32.
#define MDIM 8192
#define KDIM 32
#define RPB  256                 // rows per block
#define JSPLITS 32
#define JPB  (MDIM / JSPLITS)    // 256 j-columns per block
#define JT   16                  // j per smem tile
#define NT   (JPB / JT)          // 16 tiles
#define PJ   20                  // padded Ws row length (floats): 16B-aligned, bank-clean
#define THREADS 128

// Scratch (no device allocs): per-jsplit partials, plain stores (no atomics).
__device__ float g_wy_part[(size_t)JSPLITS * MDIM * KDIM]; // 32 MB
__device__ float g_d_part[JSPLITS * MDIM];                 // 1 MB

struct Smem {
    float Ws[2][RPB * PJ];   // [stage][row*PJ + j]   2 x 20 KB
    float Ys[2][JT * KDIM];  // [stage][j*32 + k]     2 x 2 KB
};

__device__ __forceinline__ void cp_async16(unsigned dst, const void* src) {
    asm volatile("cp.async.cg.shared.global [%0], [%1], 16;\n"
                 :: "r"(dst), "l"(src));
}
#define CP_COMMIT()  asm volatile("cp.async.commit_group;\n" ::: "memory")
#define CP_WAIT(n)   asm volatile("cp.async.wait_group %0;\n" :: "n"(n) : "memory")

__global__ void zero_out(float* __restrict__ out) { out[0] = 0.0f; }

// ---------------------------------------------------------------------------
// Main: fused rowsum + W@Y.  Thread tile: 8 rows (stride 32) x 8 k (f32x2).
// ---------------------------------------------------------------------------
__global__ void __launch_bounds__(THREADS, 4)
spectral_main(const float* __restrict__ W, const float* __restrict__ Y) {
    __shared__ Smem sm;

    const int tid    = threadIdx.x;
    const int rowgrp = tid >> 2;          // 0..31
    const int kgrp   = tid & 3;           // 0..3 -> k base = kgrp*8
    const int row0   = blockIdx.x * RPB;
    const int j0     = blockIdx.y * JPB;

    const unsigned wbase = (unsigned)__cvta_generic_to_shared(&sm.Ws[0][0]);
    const unsigned ybase = (unsigned)__cvta_generic_to_shared(&sm.Ys[0][0]);

    // staging indices
    const int lr = tid >> 2;   // staged row within 32-row group
    const int lc = tid & 3;    // 16B chunk within 64B row slice
    const int yj = tid >> 3;   // Y tile row 0..15
    const int yc = tid & 7;    // Y 16B chunk 0..7

    ull   acc[8][4];
    float dsum[8];
    #pragma unroll
    for (int p = 0; p < 8; ++p) {
        dsum[p] = 0.0f;
        #pragma unroll
        for (int q = 0; q < 4; ++q) acc[p][q] = 0ull;
    }

    // ---- tile loader (cp.async, fully coalesced 64B per row slice) ----
    auto load_tile = [&](int stage, int jt) {
        const float* wsrc = W + (size_t)row0 * MDIM + (j0 + jt * JT);
        const unsigned wdst = wbase + stage * (RPB * PJ * 4);
        #pragma unroll
        for (int i = 0; i < 8; ++i) {
            int r = lr + i * 32;
            cp_async16(wdst + (r * PJ + lc * 4) * 4,
                       wsrc + (size_t)r * MDIM + lc * 4);
        }
        cp_async16(ybase + stage * (JT * KDIM * 4) + (yj * KDIM + yc * 4) * 4,
                   Y + (size_t)(j0 + jt * JT + yj) * KDIM + yc * 4);
    };

    load_tile(0, 0);
    CP_COMMIT();

    for (int jt = 0; jt < NT; ++jt) {
        if (jt + 1 < NT) { load_tile((jt + 1) & 1, jt + 1); CP_COMMIT(); CP_WAIT(1); }
        else             { CP_WAIT(0); }
        __syncthreads();

        const float* Ws = sm.Ws[jt & 1];
        const float* Ys = sm.Ys[jt & 1];

        #pragma unroll 4
        for (int jj = 0; jj < JT; ++jj) {
            // Y pairs for this thread's 8 k (broadcast LDS.64, conflict-free)
            ull y2[4];
            #pragma unroll
            for (int q = 0; q < 4; ++q)
                y2[q] = *(const ull*)&Ys[jj * KDIM + kgrp * 8 + 2 * q];

            #pragma unroll
            for (int p = 0; p < 8; ++p) {
                float w = Ws[(rowgrp + 32 * p) * PJ + jj];   // bank-clean LDS.32
                dsum[p] += w;
                ull wd;
                asm("mov.b64 %0, {%1, %1};" : "=l"(wd) : "f"(w));
                #pragma unroll
                for (int q = 0; q < 4; ++q)
                    asm("fma.rn.f32x2 %0, %1, %2, %0;"
                        : "+l"(acc[p][q]) : "l"(wd), "l"(y2[q]));
            }
        }
        __syncthreads();   // safe to overwrite this stage next iteration
    }

    // ---- epilogue: plain vectorized stores to per-jsplit slabs ----
    float* wyp = g_wy_part + (size_t)blockIdx.y * MDIM * KDIM;
    #pragma unroll
    for (int p = 0; p < 8; ++p) {
        int r = row0 + rowgrp + 32 * p;
        ull* dst = (ull*)(wyp + (size_t)r * KDIM + kgrp * 8);
        #pragma unroll
        for (int q = 0; q < 4; ++q) dst[q] = acc[p][q];
    }
    if (kgrp == 0) {
        float* dp = g_d_part + (size_t)blockIdx.y * MDIM;
        #pragma unroll
        for (int p = 0; p < 8; ++p) dp[row0 + rowgrp + 32 * p] = dsum[p];
    }
}

// ---------------------------------------------------------------------------
// Loss: reduce 32 partials per (row,k), then loss = sum Y*(Y - WY/d) / m.
// One warp per row; lane = k. 256 threads = 8 rows per block.
// ---------------------------------------------------------------------------
__global__ void __launch_bounds__(256)
loss_kernel(const float* __restrict__ Y, float* __restrict__ out) {
    __shared__ float red[8];
    const int warp = threadIdx.x >> 5;
    const int lane = threadIdx.x & 31;
    const int row  = blockIdx.x * 8 + warp;

    // d[row] = sum over 32 jsplits (lane <-> jsplit), warp-reduce
    float d = g_d_part[lane * MDIM + row];
    #pragma unroll
    for (int o = 16; o; o >>= 1) d += __shfl_xor_sync(0xffffffffu, d, o);

    // WY[row, lane] = sum over jsplits (coalesced)
    float wy = 0.0f;
    #pragma unroll
    for (int p = 0; p < JSPLITS; ++p)
        wy += g_wy_part[((size_t)p * MDIM + row) * KDIM + lane];

    float y = Y[(size_t)row * KDIM + lane];
    float s = y * (y - wy / d);

    #pragma unroll
    for (int o = 16; o; o >>= 1) s += __shfl_xor_sync(0xffffffffu, s, o);
    if (lane == 0) red[warp] = s;
    __syncthreads();
    if (threadIdx.x < 8) {
        s = red[threadIdx.x];
        #pragma unroll
        for (int o = 4; o; o >>= 1) s += __shfl_xor_sync(0xffu, s, o);
        if (threadIdx.x == 0) atomicAdd(out, s * (1.0f / (float)MDIM));
    }
}

// ---------------------------------------------------------------------------
extern "C" void kernel_launch(void* const* d_in, const int* in_sizes, int n_in,
                              void* d_out, int out_size) {
    const float* W = (const float*)d_in[0];
    const float* Y = (const float*)d_in[1];
    float* out = (float*)d_out;

    zero_out<<<1, 1>>>(out);

    dim3 grid(MDIM / RPB, JSPLITS);   // (32, 32) = 1024 blocks
    spectral_main<<<grid, THREADS>>>(W, Y);

    loss_kernel<<<MDIM / 8, 256>>>(Y, out);
}

// round 9
// speedup vs baseline: 3.3725x; 1.6995x over previous
#include <cuda_runtime.h>
#include <cstdint>

// SpectralNetLoss: W [8192,8192] f32, Y [8192,32] f32 -> scalar f32.
// WY = W @ Y and d = W @ 1 in ONE tf32 GEMM (mma.sync, baseline sm_80 ISA —
// the harness targets sm_103 WITHOUT 'a', so no tcgen05/TMA allowed).
// B' = [Y^T ; ones] (40 x 8192, K-major). W read exactly once -> HBM-bound.

#define MDIM    8192
#define KDIM    32
#define NB      40                  // 32 Y cols + 8 ones cols (row sums d)
#define MT      128                 // rows per CTA
#define KT      32                  // K per smem stage
#define KSPLIT  4
#define KRANGE  (MDIM / KSPLIT)     // 2048
#define TILES   (KRANGE / KT)       // 64
#define STAGES  4
#define THREADS 256

#define PITCH    36                          // floats per smem row (bank-clean)
#define A_TILE_F (MT * PITCH)                // 4608 floats
#define STAGE_F  (A_TILE_F + NB * PITCH)     // 6048 floats
#define STAGE_B  (STAGE_F * 4)               // 24192 B
#define DYN_SMEM (STAGES * STAGE_B)          // 96768 B

// Scratch (no device allocs allowed).
__device__ float g_B[NB * MDIM];                      // B' K-major, 1.25 MB
__device__ float g_wy_part[KSPLIT * MDIM * KDIM];     // 4 MB
__device__ float g_d_part[KSPLIT * MDIM];             // 128 KB

__device__ __forceinline__ uint32_t smem_u32(const void* p) {
    return (uint32_t)__cvta_generic_to_shared(p);
}
__device__ __forceinline__ void cp_async16(uint32_t dst, const void* src) {
    asm volatile("cp.async.cg.shared.global [%0], [%1], 16;\n" :: "r"(dst), "l"(src));
}
#define CP_COMMIT() asm volatile("cp.async.commit_group;\n" ::: "memory")
#define CP_WAIT(n)  asm volatile("cp.async.wait_group %0;\n" :: "n"(n) : "memory")

// m16n8k8 tf32 mma (f32 bits fed directly; HW uses tf32 mantissa).
__device__ __forceinline__ void mma_tf32(float* c, const uint32_t* a, uint32_t b0,
                                         uint32_t b1) {
    asm volatile(
        "mma.sync.aligned.m16n8k8.row.col.f32.tf32.tf32.f32 "
        "{%0,%1,%2,%3}, {%4,%5,%6,%7}, {%8,%9}, {%0,%1,%2,%3};"
        : "+f"(c[0]), "+f"(c[1]), "+f"(c[2]), "+f"(c[3])
        : "r"(a[0]), "r"(a[1]), "r"(a[2]), "r"(a[3]), "r"(b0), "r"(b1));
}

// ---------------------------------------------------------------------------
// Prep: B'[n][j] = (n<32) ? Y[j][n] : 1.0f (K-major). Also zeroes out[0].
// ---------------------------------------------------------------------------
__global__ void __launch_bounds__(256)
prep_kernel(const float* __restrict__ Y, float* __restrict__ out) {
    int idx = blockIdx.x * 256 + threadIdx.x;        // 0 .. 40*8192-1
    int n = idx >> 13;
    int j = idx & (MDIM - 1);
    g_B[idx] = (n < KDIM) ? Y[(size_t)j * KDIM + n] : 1.0f;
    if (idx == 0) out[0] = 0.0f;
}

// ---------------------------------------------------------------------------
// Main GEMM: CTA computes D[128 x 40] over its K range. cp.async 4-stage
// pipeline; 8 warps x (m16 x n40); tf32 mma.sync.
// ---------------------------------------------------------------------------
__global__ void __launch_bounds__(THREADS)
mma_main(const float* __restrict__ W) {
    extern __shared__ float sm[];

    const int tid  = threadIdx.x;
    const int wid  = tid >> 5;
    const int lid  = tid & 31;
    const int g    = lid >> 2;       // group id 0..7
    const int tig  = lid & 3;        // thread in group
    const int row0 = blockIdx.x * MT;
    const int kb0  = blockIdx.y * KRANGE;

    const uint32_t sbase = smem_u32(sm);

    float acc[5][4];
    #pragma unroll
    for (int nt = 0; nt < 5; ++nt)
        #pragma unroll
        for (int q = 0; q < 4; ++q) acc[nt][q] = 0.0f;

    // ---- stage loader: W 128x32 + B' 40x32, rows padded to 144B ----
    auto load_tile = [&](int t) {
        const uint32_t sb = sbase + (t & (STAGES - 1)) * STAGE_B;
        const int      kb = kb0 + t * KT;
        #pragma unroll
        for (int p = 0; p < 4; ++p) {                    // W: 1024 x 16B chunks
            int c = tid + p * 256;
            int r = c >> 3, ci = c & 7;
            cp_async16(sb + (r * PITCH + ci * 4) * 4,
                       W + (size_t)(row0 + r) * MDIM + kb + ci * 4);
        }
        {                                                // B chunks 0..255
            int n = tid >> 3, ci = tid & 7;
            cp_async16(sb + (A_TILE_F + n * PITCH + ci * 4) * 4,
                       g_B + (size_t)n * MDIM + kb + ci * 4);
        }
        if (tid < 64) {                                  // B chunks 256..319
            int c = 256 + tid;
            int n = c >> 3, ci = c & 7;
            cp_async16(sb + (A_TILE_F + n * PITCH + ci * 4) * 4,
                       g_B + (size_t)n * MDIM + kb + ci * 4);
        }
    };

    #pragma unroll
    for (int t = 0; t < STAGES - 1; ++t) { load_tile(t); CP_COMMIT(); }

    for (int t = 0; t < TILES; ++t) {
        if (t + STAGES - 1 < TILES) load_tile(t + STAGES - 1);
        CP_COMMIT();
        CP_WAIT(STAGES - 1);                 // tile t resident
        __syncthreads();

        const float* As = sm + (t & (STAGES - 1)) * STAGE_F + wid * 16 * PITCH;
        const float* Bs = sm + (t & (STAGES - 1)) * STAGE_F + A_TILE_F;

        #pragma unroll
        for (int ks = 0; ks < 4; ++ks) {
            const int k0 = ks * 8;
            uint32_t a[4];
            a[0] = __float_as_uint(As[g * PITCH + k0 + tig]);
            a[1] = __float_as_uint(As[(g + 8) * PITCH + k0 + tig]);
            a[2] = __float_as_uint(As[g * PITCH + k0 + tig + 4]);
            a[3] = __float_as_uint(As[(g + 8) * PITCH + k0 + tig + 4]);
            #pragma unroll
            for (int nt = 0; nt < 5; ++nt) {
                uint32_t b0 = __float_as_uint(Bs[(nt * 8 + g) * PITCH + k0 + tig]);
                uint32_t b1 = __float_as_uint(Bs[(nt * 8 + g) * PITCH + k0 + tig + 4]);
                mma_tf32(acc[nt], a, b0, b1);
            }
        }
        __syncthreads();                     // all reads done before overwrite
    }

    // ---- epilogue: D fragment -> partial slabs (plain vectorized STG) ----
    // Thread holds rows (row0 + wid*16 + g) and (+8), cols 2*tig, 2*tig+1 per nt.
    const int rA = row0 + wid * 16 + g;
    const int rB = rA + 8;
    float* wyp = g_wy_part + (size_t)blockIdx.y * MDIM * KDIM;
    #pragma unroll
    for (int nt = 0; nt < 4; ++nt) {
        int col = nt * 8 + 2 * tig;
        *(float2*)&wyp[(size_t)rA * KDIM + col] = make_float2(acc[nt][0], acc[nt][1]);
        *(float2*)&wyp[(size_t)rB * KDIM + col] = make_float2(acc[nt][2], acc[nt][3]);
    }
    if (tig == 0) {                          // ones-block col 32 == row sum d
        g_d_part[blockIdx.y * MDIM + rA] = acc[4][0];
        g_d_part[blockIdx.y * MDIM + rB] = acc[4][2];
    }
}

// ---------------------------------------------------------------------------
// Loss: reduce KSPLIT partials, loss = sum Y*(Y - WY/d) / m. Warp per row.
// ---------------------------------------------------------------------------
__global__ void __launch_bounds__(256)
loss_kernel(const float* __restrict__ Y, float* __restrict__ out) {
    __shared__ float red[8];
    const int warp = threadIdx.x >> 5;
    const int lane = threadIdx.x & 31;
    const int row  = blockIdx.x * 8 + warp;

    float d = 0.0f, wy = 0.0f;
    #pragma unroll
    for (int p = 0; p < KSPLIT; ++p) {
        d  += g_d_part[p * MDIM + row];
        wy += g_wy_part[((size_t)p * MDIM + row) * KDIM + lane];
    }
    float y = Y[(size_t)row * KDIM + lane];
    float s = y * (y - wy / d);

    #pragma unroll
    for (int o = 16; o; o >>= 1) s += __shfl_xor_sync(0xffffffffu, s, o);
    if (lane == 0) red[warp] = s;
    __syncthreads();
    if (threadIdx.x < 8) {
        s = red[threadIdx.x];
        #pragma unroll
        for (int o = 4; o; o >>= 1) s += __shfl_xor_sync(0xffu, s, o);
        if (threadIdx.x == 0) atomicAdd(out, s * (1.0f / (float)MDIM));
    }
}

// ---------------------------------------------------------------------------
extern "C" void kernel_launch(void* const* d_in, const int* in_sizes, int n_in,
                              void* d_out, int out_size) {
    const float* W = (const float*)d_in[0];
    const float* Y = (const float*)d_in[1];
    float* out = (float*)d_out;

    static int attr_set = 0;
    if (!attr_set) {
        cudaFuncSetAttribute(mma_main, cudaFuncAttributeMaxDynamicSharedMemorySize,
                             DYN_SMEM);
        attr_set = 1;
    }

    prep_kernel<<<NB * MDIM / 256, 256>>>(Y, out);

    dim3 grid(MDIM / MT, KSPLIT);            // (64, 4) = 256 CTAs
    mma_main<<<grid, THREADS, DYN_SMEM>>>(W);

    loss_kernel<<<MDIM / 8, 256>>>(Y, out);
}

// round 10
// speedup vs baseline: 4.2751x; 1.2676x over previous
#include <cuda_runtime.h>
#include <cstdint>

// SpectralNetLoss: W [8192,8192] f32, Y [8192,32] f32 -> scalar f32.
// WY = W @ Y and d = W @ 1 in ONE tf32 GEMM (mma.sync m16n8k8, sm_80 baseline
// ISA — harness targets sm_103 without 'a'; tcgen05/TMA unavailable).
// B' = [Y^T ; ones] (40 x 8192) stored PRE-FRAGMENTED per 32-k tile so the
// compute loop reads B with 10 LDS.128 per warp-tile. 4 warps of m32 x n40
// minimize smem fragment-read duplication. W read exactly once -> HBM-bound.

#define MDIM    8192
#define KDIM    32
#define NB      40                  // 32 Y cols + 8 ones cols (row sums d)
#define MT      128                 // rows per CTA
#define KT      32                  // K per smem stage
#define KSPLIT  4
#define KRANGE  (MDIM / KSPLIT)     // 2048
#define TILES   (KRANGE / KT)       // 64
#define STAGES  4
#define THREADS 128

#define PITCH     36                         // W smem row pitch (bank-clean)
#define A_TILE_F  (MT * PITCH)               // 4608 floats
#define BFRAG_F   (NB * KT)                  // 1280 floats per k-tile
#define STAGE_F   (A_TILE_F + BFRAG_F)       // 5888 floats
#define STAGE_B   (STAGE_F * 4)              // 23552 B
#define DYN_SMEM  (STAGES * STAGE_B)         // 94208 B

// Scratch (no device allocs allowed).
__device__ float g_B[MDIM / KT * BFRAG_F];            // fragmented B', 1.25 MB
__device__ float g_wy_part[KSPLIT * MDIM * KDIM];     // 4 MB
__device__ float g_d_part[KSPLIT * MDIM];             // 128 KB

__device__ __forceinline__ uint32_t smem_u32(const void* p) {
    return (uint32_t)__cvta_generic_to_shared(p);
}
__device__ __forceinline__ void cp_async16(uint32_t dst, const void* src) {
    asm volatile("cp.async.cg.shared.global [%0], [%1], 16;\n" :: "r"(dst), "l"(src));
}
#define CP_COMMIT() asm volatile("cp.async.commit_group;\n" ::: "memory")
#define CP_WAIT(n)  asm volatile("cp.async.wait_group %0;\n" :: "n"(n) : "memory")

__device__ __forceinline__ void mma_tf32(float* c, const uint32_t* a, uint32_t b0,
                                         uint32_t b1) {
    asm volatile(
        "mma.sync.aligned.m16n8k8.row.col.f32.tf32.tf32.f32 "
        "{%0,%1,%2,%3}, {%4,%5,%6,%7}, {%8,%9}, {%0,%1,%2,%3};"
        : "+f"(c[0]), "+f"(c[1]), "+f"(c[2]), "+f"(c[3])
        : "r"(a[0]), "r"(a[1]), "r"(a[2]), "r"(a[3]), "r"(b0), "r"(b1));
}

// ---------------------------------------------------------------------------
// Prep: coalesced build of fragmented B'. Block b handles k-tile b
// (k in [32b, 32b+32)). Fragment flat index f -> (nt,ks2,g,tig,e):
//   f = (((nt*2+ks2)*8+g)*4+tig)*4+e
//   n = nt*8+g, k_local = (2*ks2 + (e>>1))*8 + tig + (e&1)*4
//   value = (n<32) ? Y[k][n] : 1.0f
// Compute-loop contract per (nt,ks2): thread(g,tig) LDS.128 gives
//   {B[n][ks*8+tig], B[n][ks*8+tig+4]} for ks = 2*ks2 (x,y) and 2*ks2+1 (z,w).
// ---------------------------------------------------------------------------
__global__ void __launch_bounds__(256)
prep_kernel(const float* __restrict__ Y, float* __restrict__ out) {
    __shared__ float Ys[KT][KDIM + 1];
    const int t   = blockIdx.x;          // k-tile 0..255
    const int tid = threadIdx.x;

    // Load Y rows [32t, 32t+32) x 32 cols, fully coalesced (float4 per thread).
    {
        const float4* src = (const float4*)(Y + (size_t)t * KT * KDIM);
        float4 v = src[tid];             // 256 float4 == 32x32 tile
        int j = tid >> 3, c = (tid & 7) * 4;
        Ys[j][c] = v.x; Ys[j][c + 1] = v.y; Ys[j][c + 2] = v.z; Ys[j][c + 3] = v.w;
    }
    __syncthreads();

    float* dst = g_B + (size_t)t * BFRAG_F;
    #pragma unroll
    for (int p = 0; p < BFRAG_F / 256; ++p) {        // 5 coalesced 1KB bursts
        int f   = tid + p * 256;
        int e   = f & 3;
        int tig = (f >> 2) & 3;
        int g   = (f >> 4) & 7;
        int ks2 = (f >> 7) & 1;
        int nt  = f >> 8;
        int n   = nt * 8 + g;
        int kl  = (2 * ks2 + (e >> 1)) * 8 + tig + (e & 1) * 4;
        dst[f] = (n < KDIM) ? Ys[kl][n] : 1.0f;
    }
    if (t == 0 && tid == 0) out[0] = 0.0f;
}

// ---------------------------------------------------------------------------
// Main GEMM: CTA computes D[128 x 40] over its K range. 4 warps, each
// m32 x n40. cp.async 4-stage pipeline; tf32 mma.sync.
// ---------------------------------------------------------------------------
__global__ void __launch_bounds__(THREADS)
mma_main(const float* __restrict__ W) {
    extern __shared__ float sm[];

    const int tid  = threadIdx.x;
    const int wid  = tid >> 5;           // 0..3 -> m-base wid*32
    const int lid  = tid & 31;
    const int g    = lid >> 2;
    const int tig  = lid & 3;
    const int row0 = blockIdx.x * MT;
    const int kb0  = blockIdx.y * KRANGE;
    const int tb0  = kb0 / KT;           // first global k-tile index

    const uint32_t sbase = smem_u32(sm);

    float acc[2][5][4];                  // [m16 half][n-tile][frag]
    #pragma unroll
    for (int mh = 0; mh < 2; ++mh)
        #pragma unroll
        for (int nt = 0; nt < 5; ++nt)
            #pragma unroll
            for (int q = 0; q < 4; ++q) acc[mh][nt][q] = 0.0f;

    // ---- stage loader: W 128x32 (pitch 36) + fragmented B (linear 5KB) ----
    auto load_tile = [&](int t) {
        const uint32_t sb = sbase + (t & (STAGES - 1)) * STAGE_B;
        const int      kb = kb0 + t * KT;
        #pragma unroll
        for (int p = 0; p < 8; ++p) {                    // W: 1024 x 16B chunks
            int c = tid + p * 128;
            int r = c >> 3, ci = c & 7;
            cp_async16(sb + (r * PITCH + ci * 4) * 4,
                       W + (size_t)(row0 + r) * MDIM + kb + ci * 4);
        }
        const float* bsrc = g_B + (size_t)(tb0 + t) * BFRAG_F;
        #pragma unroll
        for (int p = 0; p < 2; ++p) {                    // B chunks 0..255
            int c = tid + p * 128;
            cp_async16(sb + A_TILE_F * 4 + c * 16, bsrc + c * 4);
        }
        if (tid < 64) {                                  // B chunks 256..319
            int c = 256 + tid;
            cp_async16(sb + A_TILE_F * 4 + c * 16, bsrc + c * 4);
        }
    };

    #pragma unroll
    for (int t = 0; t < STAGES - 1; ++t) { load_tile(t); CP_COMMIT(); }

    for (int t = 0; t < TILES; ++t) {
        if (t + STAGES - 1 < TILES) load_tile(t + STAGES - 1);
        CP_COMMIT();
        CP_WAIT(STAGES - 1);                 // tile t resident
        __syncthreads();

        const float* As = sm + (t & (STAGES - 1)) * STAGE_F + (wid * 32 + g) * PITCH;
        const float* Bs = sm + (t & (STAGES - 1)) * STAGE_F + A_TILE_F;

        #pragma unroll
        for (int ks2 = 0; ks2 < 2; ++ks2) {
            // B fragments: 5 x LDS.128, conflict-free (512B contiguous/warp)
            float4 b4[5];
            #pragma unroll
            for (int nt = 0; nt < 5; ++nt)
                b4[nt] = *(const float4*)&Bs[((nt * 2 + ks2) * 32 + lid) * 4];

            #pragma unroll
            for (int sub = 0; sub < 2; ++sub) {
                const int k0 = (ks2 * 2 + sub) * 8;
                uint32_t a0[4], a1[4];       // m16 halves: rows +0/+8, +16/+24
                a0[0] = __float_as_uint(As[k0 + tig]);
                a0[1] = __float_as_uint(As[8 * PITCH + k0 + tig]);
                a0[2] = __float_as_uint(As[k0 + tig + 4]);
                a0[3] = __float_as_uint(As[8 * PITCH + k0 + tig + 4]);
                a1[0] = __float_as_uint(As[16 * PITCH + k0 + tig]);
                a1[1] = __float_as_uint(As[24 * PITCH + k0 + tig]);
                a1[2] = __float_as_uint(As[16 * PITCH + k0 + tig + 4]);
                a1[3] = __float_as_uint(As[24 * PITCH + k0 + tig + 4]);
                #pragma unroll
                for (int nt = 0; nt < 5; ++nt) {
                    uint32_t b0 = __float_as_uint(sub ? b4[nt].z : b4[nt].x);
                    uint32_t b1 = __float_as_uint(sub ? b4[nt].w : b4[nt].y);
                    mma_tf32(acc[0][nt], a0, b0, b1);
                    mma_tf32(acc[1][nt], a1, b0, b1);
                }
            }
        }
        __syncthreads();                     // all reads done before overwrite
    }

    // ---- epilogue: D fragments -> partial slabs (vectorized STG) ----
    float* wyp = g_wy_part + (size_t)blockIdx.y * MDIM * KDIM;
    #pragma unroll
    for (int mh = 0; mh < 2; ++mh) {
        const int rA = row0 + wid * 32 + mh * 16 + g;
        const int rB = rA + 8;
        #pragma unroll
        for (int nt = 0; nt < 4; ++nt) {
            int col = nt * 8 + 2 * tig;
            *(float2*)&wyp[(size_t)rA * KDIM + col] =
                make_float2(acc[mh][nt][0], acc[mh][nt][1]);
            *(float2*)&wyp[(size_t)rB * KDIM + col] =
                make_float2(acc[mh][nt][2], acc[mh][nt][3]);
        }
        if (tig == 0) {                      // ones-block: col 32 == row sum d
            g_d_part[blockIdx.y * MDIM + rA] = acc[mh][4][0];
            g_d_part[blockIdx.y * MDIM + rB] = acc[mh][4][2];
        }
    }
}

// ---------------------------------------------------------------------------
// Loss: reduce KSPLIT partials, loss = sum Y*(Y - WY/d) / m. Warp per row.
// ---------------------------------------------------------------------------
__global__ void __launch_bounds__(256)
loss_kernel(const float* __restrict__ Y, float* __restrict__ out) {
    __shared__ float red[8];
    const int warp = threadIdx.x >> 5;
    const int lane = threadIdx.x & 31;
    const int row  = blockIdx.x * 8 + warp;

    float d = 0.0f, wy = 0.0f;
    #pragma unroll
    for (int p = 0; p < KSPLIT; ++p) {
        d  += g_d_part[p * MDIM + row];
        wy += g_wy_part[((size_t)p * MDIM + row) * KDIM + lane];
    }
    float y = Y[(size_t)row * KDIM + lane];
    float s = y * (y - wy / d);

    #pragma unroll
    for (int o = 16; o; o >>= 1) s += __shfl_xor_sync(0xffffffffu, s, o);
    if (lane == 0) red[warp] = s;
    __syncthreads();
    if (threadIdx.x < 8) {
        s = red[threadIdx.x];
        #pragma unroll
        for (int o = 4; o; o >>= 1) s += __shfl_xor_sync(0xffu, s, o);
        if (threadIdx.x == 0) atomicAdd(out, s * (1.0f / (float)MDIM));
    }
}

// ---------------------------------------------------------------------------
extern "C" void kernel_launch(void* const* d_in, const int* in_sizes, int n_in,
                              void* d_out, int out_size) {
    const float* W = (const float*)d_in[0];
    const float* Y = (const float*)d_in[1];
    float* out = (float*)d_out;

    cudaFuncSetAttribute(mma_main, cudaFuncAttributeMaxDynamicSharedMemorySize,
                         DYN_SMEM);

    prep_kernel<<<MDIM / KT, 256>>>(Y, out);         // 256 blocks, one per k-tile

    dim3 grid(MDIM / MT, KSPLIT);                    // (64, 4) = 256 CTAs
    mma_main<<<grid, THREADS, DYN_SMEM>>>(W);

    loss_kernel<<<MDIM / 8, 256>>>(Y, out);
}